// round 8
// baseline (speedup 1.0000x reference)
#include <cuda_runtime.h>
#include <cstdint>

// T=8192, B=512, H=16, IN=1, OUT=5; output = FC(GRU hidden of batch index 511).
#define T_LEN 8192
#define BATCH 512
#define HID   16
#define NOUT  5

__device__ float g_hist[T_LEN * HID];

__device__ __forceinline__ float tanhap(float x) {
    float y; asm("tanh.approx.f32 %0, %1;" : "=f"(y) : "f"(x)); return y;
}
__device__ __forceinline__ unsigned long long pk2(float lo, float hi) {
    unsigned long long r; asm("mov.b64 %0, {%1, %2};" : "=l"(r) : "f"(lo), "f"(hi)); return r;
}
__device__ __forceinline__ void upk2(float& lo, float& hi, unsigned long long v) {
    asm("mov.b64 {%0, %1}, %2;" : "=f"(lo), "=f"(hi) : "l"(v));
}
__device__ __forceinline__ unsigned long long fma2(unsigned long long a, unsigned long long b,
                                                   unsigned long long c) {
    unsigned long long d;
    asm("fma.rn.f32x2 %0, %1, %2, %3;" : "=l"(d) : "l"(a), "l"(b), "l"(c));
    return d;
}
__device__ __forceinline__ unsigned long long add2(unsigned long long a, unsigned long long b) {
    unsigned long long d;
    asm("add.rn.f32x2 %0, %1, %2;" : "=l"(d) : "l"(a), "l"(b));
    return d;
}

__global__ void __launch_bounds__(32, 1)
gru_seq_kernel(const float* __restrict__ x,
               const float* __restrict__ w_ih,
               const float* __restrict__ w_hh,
               const float* __restrict__ b_ih,
               const float* __restrict__ b_hh)
{
    __shared__ __align__(16) float hbuf[16];
    const unsigned FULL = 0xffffffffu;
    const int lane = threadIdx.x;
    const int j    = lane & 15;   // lanes j and j+16 do identical work

    // sigmoid(v) = 0.5 + 0.5*tanh(v/2): r/z rows pre-halved.
    // n: narg = xgn + D + t_r*D with D = 0.5*(w_n.h + b_n).
    unsigned long long wr[8], wz[8], wn[8];
    #pragma unroll
    for (int k = 0; k < 8; ++k) {
        const float* rr = &w_hh[j * HID];
        const float* rz = &w_hh[(HID + j) * HID];
        const float* rn = &w_hh[(2 * HID + j) * HID];
        wr[k] = pk2(0.5f * rr[2 * k], 0.5f * rr[2 * k + 1]);
        wz[k] = pk2(0.5f * rz[2 * k], 0.5f * rz[2 * k + 1]);
        wn[k] = pk2(0.5f * rn[2 * k], 0.5f * rn[2 * k + 1]);
    }
    const float wih_r2  = 0.5f * w_ih[j];
    const float bias_r2 = 0.5f * (b_ih[j] + b_hh[j]);
    const float wih_z2  = 0.5f * w_ih[HID + j];
    const float bias_z2 = 0.5f * (b_ih[HID + j] + b_hh[HID + j]);
    const float wih_n   = w_ih[2 * HID + j];
    const float bih_n   = b_ih[2 * HID + j];
    const unsigned long long bn2pk = pk2(0.5f * b_hh[2 * HID + j], 0.0f);
    const unsigned long long Z64 = 0ull;

    if (lane < 16) hbuf[j] = 0.0f;
    __syncwarp();
    float h_own = 0.0f;

    uint32_t sbase;
    asm("{ .reg .u64 t; cvta.to.shared.u64 t, %1; cvt.u32.u64 %0, t; }"
        : "=r"(sbase) : "l"(&hbuf[0]));
    const uint32_t waddr = sbase + (uint32_t)(j * 4);

    float* histp = &g_hist[j];

    const int xoff = BATCH - 1;
    float xv      = x[(0  + lane) * BATCH + xoff];
    float xv_next = x[(32 + lane) * BATCH + xoff];

    const int NCHUNK = T_LEN / 32;
    for (int c = 0; c < NCHUNK; ++c) {
        #pragma unroll
        for (int s = 0; s < 32; ++s) {
            // warp-synchronous single-buffer roundtrip (in-order smem pipeline)
            unsigned long long h0, h1, h2, h3, h4, h5, h6, h7;
            asm volatile("ld.shared.v2.u64 {%0, %1}, [%2];" : "=l"(h0), "=l"(h1) : "r"(sbase));
            asm volatile("ld.shared.v2.u64 {%0, %1}, [%2];" : "=l"(h2), "=l"(h3) : "r"(sbase + 16));
            asm volatile("ld.shared.v2.u64 {%0, %1}, [%2];" : "=l"(h4), "=l"(h5) : "r"(sbase + 32));
            asm volatile("ld.shared.v2.u64 {%0, %1}, [%2];" : "=l"(h6), "=l"(h7) : "r"(sbase + 48));

            // x-gate terms: ready (~+30) well before LDS data (~+80)
            const float xt  = __shfl_sync(FULL, xv, s);
            const float xgr = fmaf(xt, wih_r2, bias_r2);
            const float xgz = fmaf(xt, wih_z2, bias_z2);
            const float xgn = fmaf(xt, wih_n,  bih_n);
            const unsigned long long seed_r = pk2(xgr, 0.0f);
            const unsigned long long seed_z = pk2(xgz, 0.0f);

            // --- PRIORITY SCHEDULE: all r-fma2 first (binding chain), then n, then z.
            // Two accumulators per chain: reuse gap = 2 instrs = 4 cyc = FMA lat -> no bubbles.
            unsigned long long ar0, ar1;
            ar0 = fma2(wr[0], h0, seed_r); ar1 = fma2(wr[1], h1, Z64);
            ar0 = fma2(wr[2], h2, ar0);    ar1 = fma2(wr[3], h3, ar1);
            ar0 = fma2(wr[4], h4, ar0);    ar1 = fma2(wr[5], h5, ar1);
            ar0 = fma2(wr[6], h6, ar0);    ar1 = fma2(wr[7], h7, ar1);
            float lo, hi;
            upk2(lo, hi, add2(ar0, ar1)); const float gr = lo + hi;   // includes xgr
            const float t_r = tanhap(gr);

            unsigned long long an0, an1;
            an0 = fma2(wn[0], h0, bn2pk);  an1 = fma2(wn[1], h1, Z64);
            an0 = fma2(wn[2], h2, an0);    an1 = fma2(wn[3], h3, an1);
            an0 = fma2(wn[4], h4, an0);    an1 = fma2(wn[5], h5, an1);
            an0 = fma2(wn[6], h6, an0);    an1 = fma2(wn[7], h7, an1);
            upk2(lo, hi, add2(an0, an1)); const float D = lo + hi;    // 0.5*(w_n.h+b_n)
            const float xnD  = xgn + D;                 // hidden under t_r MUFU
            const float narg = fmaf(t_r, D, xnD);
            const float n    = tanhap(narg);

            unsigned long long az0, az1;
            az0 = fma2(wz[0], h0, seed_z); az1 = fma2(wz[1], h1, Z64);
            az0 = fma2(wz[2], h2, az0);    az1 = fma2(wz[3], h3, az1);
            az0 = fma2(wz[4], h4, az0);    az1 = fma2(wz[5], h5, az1);
            az0 = fma2(wz[6], h6, az0);    az1 = fma2(wz[7], h7, az1);
            upk2(lo, hi, add2(az0, az1)); const float gz = lo + hi;   // includes xgz
            const float t_z = tanhap(gz);              // overlaps tanh_n
            const float zg  = fmaf(0.5f, t_z, 0.5f);
            const float omz = fmaf(-0.5f, t_z, 0.5f);
            const float zh  = zg * h_own;

            const float hn  = fmaf(n, omz, zh);        // single FMA after tanh_n
            h_own = hn;

            asm volatile("st.shared.f32 [%0], %1;" :: "r"(waddr), "f"(hn));
            *histp = hn;
            histp += HID;
        }
        xv = xv_next;
        const int nc = (c + 2 < NCHUNK) ? (c + 2) : (NCHUNK - 1);   // branch-free
        xv_next = x[(nc * 32 + lane) * BATCH + xoff];
    }
}

// out[t][o] = h_t . fc_w[o] + fc_b[o]
__global__ void fc_kernel(const float* __restrict__ fc_w,
                          const float* __restrict__ fc_b,
                          float* __restrict__ out)
{
    const int i = blockIdx.x * blockDim.x + threadIdx.x;
    if (i >= T_LEN * NOUT) return;
    const int t = i / NOUT;
    const int o = i - t * NOUT;
    const float* hrow = &g_hist[t * HID];
    float acc = fc_b[o];
    #pragma unroll
    for (int k = 0; k < HID; ++k)
        acc = fmaf(hrow[k], fc_w[o * HID + k], acc);
    out[i] = acc;
}

extern "C" void kernel_launch(void* const* d_in, const int* in_sizes, int n_in,
                              void* d_out, int out_size)
{
    const float* x    = (const float*)d_in[0];
    const float* w_ih = (const float*)d_in[1];
    const float* w_hh = (const float*)d_in[2];
    const float* b_ih = (const float*)d_in[3];
    const float* b_hh = (const float*)d_in[4];
    const float* fc_w = (const float*)d_in[5];
    const float* fc_b = (const float*)d_in[6];
    float* out = (float*)d_out;

    gru_seq_kernel<<<1, 32>>>(x, w_ih, w_hh, b_ih, b_hh);

    const int n = T_LEN * NOUT;
    fc_kernel<<<(n + 255) / 256, 256>>>(fc_w, fc_b, out);
}

// round 9
// speedup vs baseline: 1.0315x; 1.0315x over previous
#include <cuda_runtime.h>
#include <cstdint>

// T=8192, B=512, H=16, IN=1, OUT=5; output = FC(GRU hidden of batch index 511).
#define T_LEN 8192
#define BATCH 512
#define HID   16
#define NOUT  5

// Transposed history: g_hist[j * T_LEN + t]  (lane-contiguous in t -> STG.128 x1 per 4 steps)
__device__ float g_hist[HID * T_LEN];

__device__ __forceinline__ float tanhap(float x) {
    float y; asm("tanh.approx.f32 %0, %1;" : "=f"(y) : "f"(x)); return y;
}
__device__ __forceinline__ unsigned long long pk2(float lo, float hi) {
    unsigned long long r; asm("mov.b64 %0, {%1, %2};" : "=l"(r) : "f"(lo), "f"(hi)); return r;
}
__device__ __forceinline__ void upk2(float& lo, float& hi, unsigned long long v) {
    asm("mov.b64 {%0, %1}, %2;" : "=f"(lo), "=f"(hi) : "l"(v));
}
__device__ __forceinline__ unsigned long long fma2(unsigned long long a, unsigned long long b,
                                                   unsigned long long c) {
    unsigned long long d;
    asm("fma.rn.f32x2 %0, %1, %2, %3;" : "=l"(d) : "l"(a), "l"(b), "l"(c));
    return d;
}
__device__ __forceinline__ unsigned long long add2(unsigned long long a, unsigned long long b) {
    unsigned long long d;
    asm("add.rn.f32x2 %0, %1, %2;" : "=l"(d) : "l"(a), "l"(b));
    return d;
}

__global__ void __launch_bounds__(32, 1)
gru_seq_kernel(const float* __restrict__ x,
               const float* __restrict__ w_ih,
               const float* __restrict__ w_hh,
               const float* __restrict__ b_ih,
               const float* __restrict__ b_hh)
{
    __shared__ __align__(16) float hbuf[16];
    const unsigned FULL = 0xffffffffu;
    const int lane = threadIdx.x;
    const int j    = lane & 15;   // lanes j and j+16 do identical work

    // sigmoid(v) = 0.5 + 0.5*tanh(v/2): r/z rows pre-halved.
    // n: narg = xgn + D + t_r*D with D = 0.5*(w_n.h + b_n).
    unsigned long long wr[8], wz[8], wn[8];
    #pragma unroll
    for (int k = 0; k < 8; ++k) {
        const float* rr = &w_hh[j * HID];
        const float* rz = &w_hh[(HID + j) * HID];
        const float* rn = &w_hh[(2 * HID + j) * HID];
        wr[k] = pk2(0.5f * rr[2 * k], 0.5f * rr[2 * k + 1]);
        wz[k] = pk2(0.5f * rz[2 * k], 0.5f * rz[2 * k + 1]);
        wn[k] = pk2(0.5f * rn[2 * k], 0.5f * rn[2 * k + 1]);
    }
    const float wih_r2  = 0.5f * w_ih[j];
    const float bias_r2 = 0.5f * (b_ih[j] + b_hh[j]);
    const float wih_z2  = 0.5f * w_ih[HID + j];
    const float bias_z2 = 0.5f * (b_ih[HID + j] + b_hh[HID + j]);
    const float wih_n   = w_ih[2 * HID + j];
    const float bih_n   = b_ih[2 * HID + j];
    const unsigned long long bn2pk = pk2(0.5f * b_hh[2 * HID + j], 0.0f);
    const unsigned long long Z64 = 0ull;

    if (lane < 16) hbuf[j] = 0.0f;
    __syncwarp();
    float h_own = 0.0f;

    uint32_t sbase;
    asm("{ .reg .u64 t; cvta.to.shared.u64 t, %1; cvt.u32.u64 %0, t; }"
        : "=r"(sbase) : "l"(&hbuf[0]));
    const uint32_t waddr = sbase + (uint32_t)(j * 4);

    float4* histp = (float4*)&g_hist[j * T_LEN];   // transposed row, 16B-aligned
    float4 hacc;                                    // 4-step history batch

    const int xoff = BATCH - 1;
    float xv      = x[(0  + lane) * BATCH + xoff];
    float xv_next = x[(32 + lane) * BATCH + xoff];

    const int NCHUNK = T_LEN / 32;
    for (int c = 0; c < NCHUNK; ++c) {
        #pragma unroll
        for (int s = 0; s < 32; ++s) {
            // warp-synchronous single-buffer roundtrip (in-order smem pipeline)
            unsigned long long h0, h1, h2, h3, h4, h5, h6, h7;
            asm volatile("ld.shared.v2.u64 {%0, %1}, [%2];" : "=l"(h0), "=l"(h1) : "r"(sbase));
            asm volatile("ld.shared.v2.u64 {%0, %1}, [%2];" : "=l"(h2), "=l"(h3) : "r"(sbase + 16));
            asm volatile("ld.shared.v2.u64 {%0, %1}, [%2];" : "=l"(h4), "=l"(h5) : "r"(sbase + 32));
            asm volatile("ld.shared.v2.u64 {%0, %1}, [%2];" : "=l"(h6), "=l"(h7) : "r"(sbase + 48));

            // x-gate terms: ready well before LDS data
            const float xt  = __shfl_sync(FULL, xv, s);
            const float xgr = fmaf(xt, wih_r2, bias_r2);
            const float xgz = fmaf(xt, wih_z2, bias_z2);
            const float xgn = fmaf(xt, wih_n,  bih_n);
            const unsigned long long seed_r = pk2(xgr, 0.0f);
            const unsigned long long seed_z = pk2(xgz, 0.0f);

            unsigned long long ar0, ar1, az0, az1, an0, an1;
            ar0 = fma2(wr[0], h0, seed_r); ar1 = fma2(wr[1], h1, Z64);
            an0 = fma2(wn[0], h0, bn2pk);  an1 = fma2(wn[1], h1, Z64);
            az0 = fma2(wz[0], h0, seed_z); az1 = fma2(wz[1], h1, Z64);
            ar0 = fma2(wr[2], h2, ar0);    ar1 = fma2(wr[3], h3, ar1);
            an0 = fma2(wn[2], h2, an0);    an1 = fma2(wn[3], h3, an1);
            az0 = fma2(wz[2], h2, az0);    az1 = fma2(wz[3], h3, az1);
            ar0 = fma2(wr[4], h4, ar0);    ar1 = fma2(wr[5], h5, ar1);
            an0 = fma2(wn[4], h4, an0);    an1 = fma2(wn[5], h5, an1);
            az0 = fma2(wz[4], h4, az0);    az1 = fma2(wz[5], h5, az1);
            ar0 = fma2(wr[6], h6, ar0);    ar1 = fma2(wr[7], h7, ar1);
            an0 = fma2(wn[6], h6, an0);    an1 = fma2(wn[7], h7, an1);
            az0 = fma2(wz[6], h6, az0);    az1 = fma2(wz[7], h7, az1);

            float lo, hi;
            upk2(lo, hi, add2(ar0, ar1)); const float gr = lo + hi;   // includes xgr
            upk2(lo, hi, add2(an0, an1)); const float D  = lo + hi;   // 0.5*(w_n.h+b_n)
            upk2(lo, hi, add2(az0, az1)); const float gz = lo + hi;   // includes xgz

            const float t_r = tanhap(gr);
            const float t_z = tanhap(gz);
            const float xnD = xgn + D;                 // hidden under t_r MUFU
            const float zg  = fmaf(0.5f, t_z, 0.5f);
            const float omz = fmaf(-0.5f, t_z, 0.5f);
            const float zh  = zg * h_own;

            const float narg = fmaf(t_r, D, xnD);
            const float n    = tanhap(narg);
            const float hn   = fmaf(n, omz, zh);       // single FMA after tanh_n
            h_own = hn;

            asm volatile("st.shared.f32 [%0], %1;" :: "r"(waddr), "f"(hn));

            // batch history: one STG.128 per 4 steps (off the critical path)
            if ((s & 3) == 0) hacc.x = hn;
            else if ((s & 3) == 1) hacc.y = hn;
            else if ((s & 3) == 2) hacc.z = hn;
            else { hacc.w = hn; *histp = hacc; ++histp; }
        }
        xv = xv_next;
        const int nc = (c + 2 < NCHUNK) ? (c + 2) : (NCHUNK - 1);   // branch-free
        xv_next = x[(nc * 32 + lane) * BATCH + xoff];
    }
}

// out[t][o] = h_t . fc_w[o] + fc_b[o]   (history is [k][t] transposed)
__global__ void fc_kernel(const float* __restrict__ fc_w,
                          const float* __restrict__ fc_b,
                          float* __restrict__ out)
{
    const int i = blockIdx.x * blockDim.x + threadIdx.x;
    if (i >= T_LEN * NOUT) return;
    const int t = i / NOUT;
    const int o = i - t * NOUT;
    float acc = fc_b[o];
    #pragma unroll
    for (int k = 0; k < HID; ++k)
        acc = fmaf(g_hist[k * T_LEN + t], fc_w[o * HID + k], acc);
    out[i] = acc;
}

extern "C" void kernel_launch(void* const* d_in, const int* in_sizes, int n_in,
                              void* d_out, int out_size)
{
    const float* x    = (const float*)d_in[0];
    const float* w_ih = (const float*)d_in[1];
    const float* w_hh = (const float*)d_in[2];
    const float* b_ih = (const float*)d_in[3];
    const float* b_hh = (const float*)d_in[4];
    const float* fc_w = (const float*)d_in[5];
    const float* fc_b = (const float*)d_in[6];
    float* out = (float*)d_out;

    gru_seq_kernel<<<1, 32>>>(x, w_ih, w_hh, b_ih, b_hh);

    const int n = T_LEN * NOUT;
    fc_kernel<<<(n + 255) / 256, 256>>>(fc_w, fc_b, out);
}